// round 13
// baseline (speedup 1.0000x reference)
#include <cuda_runtime.h>
#include <cuda_bf16.h>
#include <cstdint>

// ---------------- problem constants ----------------
#define Bb 512
#define Nn 100
#define Tt 100
#define Mm (Bb*Nn)            // 51200
#define OFF_RECON  (Mm*Tt)
#define OFF_VQ     (Mm*Tt + 1)
#define OFF_IDX    (Mm*Tt + 2)
#define OUT_FULL   (Mm*Tt + 2 + Mm)

typedef unsigned long long u64;

// ---------------- scratch ----------------
__device__ __align__(16) float g_z[Mm*128];
__device__ int   g_idx[Mm];
__device__ __align__(16) float4 g_w4a[64*32];        // [ic][lane] = {w0A,w0B,w1A,w1B}
__device__ __align__(16) float2 g_w4b[64*32];        // [ic][lane] = {w2A,w2B}
__device__ __align__(16) float g_latT[64*128];
__device__ __align__(16) float g_cbP[512*128];
__device__ float g_cbnorm[512];
__device__ __align__(16) float g_d1T[128*256];
__device__ __align__(16) float g_d2T[256*256];
__device__ __align__(16) float g_d3T[256*100];
__device__ float g_decoded[513*100];
__device__ float g_vqpart[3200];
__device__ float g_rpart[6400*3];
__device__ int g_bcnt[50];
__device__ int g_cidx[Mm];
__device__ int g_nact;

// ---------------- f32x2 helpers ----------------
__device__ __forceinline__ u64 pack2(float a, float b){
    u64 r; asm("mov.b64 %0, {%1,%2};" : "=l"(r) : "f"(a), "f"(b)); return r;
}
__device__ __forceinline__ void ffma2(u64 &d, u64 a, u64 b){
    asm("fma.rn.f32x2 %0, %1, %2, %0;" : "+l"(d) : "l"(a), "l"(b));
}
__device__ __forceinline__ float2 unpack2(u64 v){
    float2 f; asm("mov.b64 {%0,%1}, %2;" : "=f"(f.x), "=f"(f.y) : "l"(v)); return f;
}

// ---------------- prep ----------------
__global__ void prep_kernel(const float* __restrict__ c2w, const float* __restrict__ latw,
                            const float* __restrict__ cb,  const float* __restrict__ d1w,
                            const float* __restrict__ d2w, const float* __restrict__ d3w){
    int gt = blockIdx.x*blockDim.x + threadIdx.x;
    int nt = gridDim.x*blockDim.x;
    for (int i=gt; i<64*32; i+=nt){
        int lane = i & 31; int ic = i >> 5;
        g_w4a[i] = make_float4(c2w[lane*192 + ic*3 + 0], c2w[(lane+32)*192 + ic*3 + 0],
                               c2w[lane*192 + ic*3 + 1], c2w[(lane+32)*192 + ic*3 + 1]);
        g_w4b[i] = make_float2(c2w[lane*192 + ic*3 + 2], c2w[(lane+32)*192 + ic*3 + 2]);
    }
    for (int i=gt; i<64*128; i+=nt){
        int e = i & 127; int oc = i >> 7;
        g_latT[i] = latw[e*64 + oc];
    }
    for (int i=gt; i<512*128; i+=nt){
        int j = i & 3; int r = i >> 2; int e = r & 511; int d4 = r >> 9;
        g_cbP[i] = cb[e*128 + d4*4 + j];
    }
    for (int e=gt; e<512; e+=nt){
        float s = 0.f;
        for (int d=0; d<128; d++){ float v = cb[e*128+d]; s = fmaf(v,v,s); }
        g_cbnorm[e] = s;
    }
    for (int i=gt; i<128*256; i+=nt){ int j=i&255; int k=i>>8; g_d1T[i] = d1w[j*128+k]; }
    for (int i=gt; i<256*256; i+=nt){ int j=i&255; int k=i>>8; g_d2T[i] = d2w[j*256+k]; }
    for (int i=gt; i<256*100; i+=nt){ int j=i%100; int k=i/100; g_d3T[i] = d3w[j*256+k]; }
}

// ---------------- compaction ----------------
__global__ void __launch_bounds__(1024) compactA(const float* __restrict__ imask){
    __shared__ int wc[32];
    const int tid = threadIdx.x;
    const int m = blockIdx.x*1024 + tid;
    unsigned b = __ballot_sync(0xFFFFFFFFu, imask[m] != 0.f);
    if ((tid & 31) == 0) wc[tid>>5] = __popc(b);
    __syncthreads();
    if (tid == 0){
        int s = 0;
        #pragma unroll
        for (int i=0;i<32;i++) s += wc[i];
        g_bcnt[blockIdx.x] = s;
    }
}

__global__ void __launch_bounds__(1024) compactC(const float* __restrict__ imask){
    __shared__ int woff[32];
    __shared__ int sbase;
    const int tid = threadIdx.x;
    const int bid = blockIdx.x;
    const int m = bid*1024 + tid;
    const bool act = imask[m] != 0.f;
    unsigned b = __ballot_sync(0xFFFFFFFFu, act);
    if ((tid & 31) == 0) woff[tid>>5] = __popc(b);
    __syncthreads();
    if (tid == 0){
        int base = 0;
        for (int i=0;i<bid;i++) base += g_bcnt[i];
        sbase = base;
        int run = 0;
        #pragma unroll
        for (int w=0;w<32;w++){ int c = woff[w]; woff[w] = run; run += c; }
        if (bid == 0){
            int tot = 0;
            #pragma unroll
            for (int i=0;i<50;i++) tot += g_bcnt[i];
            g_nact = tot;
        }
    }
    __syncthreads();
    if (act){
        int rank = __popc(b & ((1u << (tid & 31)) - 1u));
        g_cidx[sbase + woff[tid>>5] + rank] = m;
    }
}

// ---------------- encoder: 4 instances/block sequentially, prefetched xs ----------------
#define HROW 52   // mod 4 == 0 -> 16B-aligned rows; gcd(52,32)=4
#define NI 4
// shh: h[l] at q=l (q in [0,49]); shs: h[l] at q=l+1, pads q=0 (h[-1]=0), q=51 (h[50]=0)

template<int NP>
__device__ __forceinline__ void conv2_tile(int lane, int l0, u64 bbA, u64 bbB,
                                           const float* __restrict__ shh,
                                           const float* __restrict__ shs,
                                           float &outA, float &outB){
    constexpr int NK = NP/2;
    u64 accA[NP], accB[NP];
    #pragma unroll
    for (int p=0;p<NP;p++){ accA[p]=bbA; accB[p]=bbB; }
    #pragma unroll 2
    for (int ic=0; ic<64; ic++){
        float4 w01 = g_w4a[ic*32 + lane];
        float2 w2  = g_w4b[ic*32 + lane];
        u64 W0a = pack2(w01.x,w01.x), W0b = pack2(w01.y,w01.y);
        u64 W1a = pack2(w01.z,w01.z), W1b = pack2(w01.w,w01.w);
        u64 W2a = pack2(w2.x,w2.x),   W2b = pack2(w2.y,w2.y);
        const float* hr = shh + ic*HROW + l0;
        const float* sr = shs + ic*HROW + l0;
        ulonglong2 Sc = *(const ulonglong2*)(sr);
        #pragma unroll
        for (int k=0;k<NK;k++){
            ulonglong2 A2 = *(const ulonglong2*)(hr + 4*k);
            ulonglong2 Sn = *(const ulonglong2*)(sr + 4*k + 4);
            const int p = 2*k;
            ffma2(accA[p], W0a, Sc.x); ffma2(accB[p], W0b, Sc.x);
            ffma2(accA[p], W1a, A2.x); ffma2(accB[p], W1b, A2.x);
            ffma2(accA[p], W2a, Sc.y); ffma2(accB[p], W2b, Sc.y);
            ffma2(accA[p+1], W0a, Sc.y); ffma2(accB[p+1], W0b, Sc.y);
            ffma2(accA[p+1], W1a, A2.y); ffma2(accB[p+1], W1b, A2.y);
            ffma2(accA[p+1], W2a, Sn.x); ffma2(accB[p+1], W2b, Sn.x);
            Sc = Sn;
        }
        if (NP & 1){
            const int p = NP - 1;
            u64 Atl = *(const u64*)(hr + 2*p);
            ffma2(accA[p], W0a, Sc.x); ffma2(accB[p], W0b, Sc.x);
            ffma2(accA[p], W1a, Atl);  ffma2(accB[p], W1b, Atl);
            ffma2(accA[p], W2a, Sc.y); ffma2(accB[p], W2b, Sc.y);
        }
    }
    float sA = 0.f, sB = 0.f;
    #pragma unroll
    for (int p=0;p<NP;p++){
        float2 fa = unpack2(accA[p]);
        float2 fb = unpack2(accB[p]);
        sA += fmaxf(fa.x,0.f) + fmaxf(fa.y,0.f);
        sB += fmaxf(fb.x,0.f) + fmaxf(fb.y,0.f);
    }
    outA = sA; outB = sB;
}

__global__ void __launch_bounds__(128) enc_kernel(const float* __restrict__ x,
                                                  const float* __restrict__ traj,
                                                  const float* __restrict__ imask,
                                                  const float* __restrict__ c1w,
                                                  const float* __restrict__ c1b,
                                                  const float* __restrict__ c2b,
                                                  const float* __restrict__ latb){
    __shared__ __align__(16) float xs[2][112];
    __shared__ __align__(16) float shh[64*HROW];
    __shared__ __align__(16) float shs[64*HROW];
    __shared__ float phm[4][64];
    __shared__ float hms[64];
    const int tid = threadIdx.x;
    const int nact = g_nact;
    const int s0 = blockIdx.x*NI;
    if (s0 >= nact) return;

    const int oc = tid & 63, half = tid >> 6;
    const int wid = tid >> 5, lane = tid & 31;

    // one-time: pads (q=0 and q=51 of shs, all 64 rows)
    {
        int r = tid >> 1;
        int q = (tid & 1) ? 51 : 0;
        shs[r*HROW + q] = 0.f;
    }
    // one-time: conv1 + conv2 constants
    float w1r[6];
    #pragma unroll
    for (int j=0;j<6;j++) w1r[j] = c1w[oc*6 + (j&1)*3 + (j>>1)];
    const float b1v = c1b[oc];
    const float bA = c2b[lane], bB = c2b[lane+32];
    const u64 bbA = pack2(bA,bA), bbB = pack2(bB,bB);

    // prefetch instance 0 into xs[0]
    int m_cur = g_cidx[s0];
    if (tid < 112){
        float v = 0.f;
        if (tid >= 2 && tid < 102) v = x[m_cur*100 + tid - 2] * traj[m_cur*100 + tid - 2] * imask[m_cur];
        xs[0][tid] = v;
    }
    __syncthreads();

    #pragma unroll 1
    for (int i = 0; i < NI; i++){
        const int s = s0 + i;
        if (s >= nact) break;                  // uniform across block
        const int m = m_cur;
        const float im = imask[m];             // 1.0 for active

        // prefetch next instance into the other buffer (visible after post-conv1 sync)
        const int sn = s + 1;
        if (i + 1 < NI && sn < nact){
            int mn = g_cidx[sn];
            m_cur = mn;
            if (tid < 112){
                float v = 0.f;
                if (tid >= 2 && tid < 102) v = x[mn*100 + tid - 2] * traj[mn*100 + tid - 2] * imask[mn];
                xs[(i+1)&1][tid] = v;
            }
        }

        // conv1 with float2 sliding window (reads xs[i&1])
        {
            const float* xi = xs[i&1];
            const int ls = half ? 26 : 0, le = half ? 50 : 26;
            float* dh = shh + oc*HROW;       // h[l] at q=l
            float* ds = shs + oc*HROW + 1;   // h[l] at q=l+1
            float2 p0 = *(const float2*)(xi + 2*ls);
            float2 p1 = *(const float2*)(xi + 2*ls + 2);
            float2 p2 = *(const float2*)(xi + 2*ls + 4);
            #pragma unroll 2
            for (int l=ls; l<le; l++){
                float a = b1v;
                a = fmaf(w1r[0], p0.x, a);
                a = fmaf(w1r[1], p0.y, a);
                a = fmaf(w1r[2], p1.x, a);
                a = fmaf(w1r[3], p1.y, a);
                a = fmaf(w1r[4], p2.x, a);
                a = fmaf(w1r[5], p2.y, a);
                a = fmaxf(a, 0.f);
                dh[l] = a;
                ds[l] = a;
                p0 = p1; p1 = p2;
                if (l+1 < le) p2 = *(const float2*)(xi + 2*(l+1) + 4);
            }
        }
        __syncthreads();

        // conv2: warp w -> l0 {0,12,24,36}, NP {6,6,6,7}
        float sA, sB;
        if      (wid == 0) conv2_tile<6>(lane, 0,  bbA, bbB, shh, shs, sA, sB);
        else if (wid == 1) conv2_tile<6>(lane, 12, bbA, bbB, shh, shs, sA, sB);
        else if (wid == 2) conv2_tile<6>(lane, 24, bbA, bbB, shh, shs, sA, sB);
        else               conv2_tile<7>(lane, 36, bbA, bbB, shh, shs, sA, sB);
        phm[wid][lane]      = sA;
        phm[wid][lane + 32] = sB;
        __syncthreads();
        if (tid < 64)
            hms[tid] = (((phm[0][tid] + phm[1][tid]) + phm[2][tid]) + phm[3][tid]) * (1.f/50.f);
        __syncthreads();

        // latent
        float acc = latb[tid];
        #pragma unroll 4
        for (int o2=0; o2<64; o2++) acc = fmaf(g_latT[o2*128 + tid], hms[o2], acc);
        g_z[m*128 + tid] = acc * im;
        __syncthreads();                       // hms consumed before next iter overwrites
    }
}

// ---------------- VQ (unchanged; reference-matched rounding) ----------------
__global__ void __launch_bounds__(512) vq_kernel(const float* __restrict__ imask){
    __shared__ __align__(16) float zsh[16*128];
    __shared__ u64 smin[16];
    __shared__ float znorm[16];
    __shared__ float vqs[16];
    __shared__ int msh[16];
    __shared__ int vld[16];
    const int tid = threadIdx.x;
    const int blk = blockIdx.x;
    const int nact = g_nact;
    const int s0 = blk * 16;
    if (s0 >= nact){
        if (tid == 0) g_vqpart[blk] = 0.f;
        return;
    }
    if (tid < 16){
        int s = s0 + tid;
        int valid = (s < nact);
        msh[tid] = valid ? g_cidx[s] : g_cidx[0];
        vld[tid] = valid;
        smin[tid] = ~0ULL;
    }
    __syncthreads();
    for (int i=tid; i<2048; i+=512){
        int m = msh[i >> 7];
        zsh[i] = 2.0f * g_z[m*128 + (i & 127)];
    }
    __syncthreads();

    const int wid = tid >> 5, lane = tid & 31;
    {
        float s = 0.f;
        #pragma unroll
        for (int d=lane; d<128; d+=32){ float v = zsh[wid*128 + d]; s = fmaf(v,v,s); }
        #pragma unroll
        for (int o=16;o;o>>=1) s += __shfl_down_sync(0xFFFFFFFFu, s, o);
        if (lane == 0) znorm[wid] = 0.25f * s;
    }
    __syncthreads();

    const int e = tid;
    u64 acc[16];
    #pragma unroll
    for (int g=0; g<16; g++) acc[g] = 0ULL;
    #pragma unroll 1
    for (int d4=0; d4<32; d4++){
        ulonglong2 cbp = *(const ulonglong2*)(g_cbP + (d4*512 + e)*4);
        #pragma unroll
        for (int g=0; g<16; g++){
            ulonglong2 zz = *(const ulonglong2*)(zsh + g*128 + d4*4);
            ffma2(acc[g], cbp.x, zz.x);
            ffma2(acc[g], cbp.y, zz.y);
        }
    }
    const float cbn = g_cbnorm[e];
    #pragma unroll
    for (int g=0; g<16; g++){
        float2 a = unpack2(acc[g]);
        float dot2 = a.x + a.y;
        float t1 = znorm[g] - dot2;
        float d  = t1 + cbn;
        unsigned u = __float_as_uint(d);
        unsigned mono = (u & 0x80000000u) ? ~u : (u | 0x80000000u);
        u64 key = ((u64)mono << 32) | (unsigned)e;
        #pragma unroll
        for (int o=16;o;o>>=1){
            u64 other = __shfl_down_sync(0xFFFFFFFFu, key, o);
            key = (other < key) ? other : key;
        }
        if (lane == 0) atomicMin(&smin[g], key);
    }
    __syncthreads();
    if (tid < 16){
        const int g = tid;
        u64 key = smin[g];
        unsigned mono = (unsigned)(key >> 32);
        unsigned u = (mono & 0x80000000u) ? (mono ^ 0x80000000u) : ~mono;
        float d = __uint_as_float(u);
        int idx = (int)(key & 0xFFFFFFFFu);
        if (vld[g]){
            g_idx[msh[g]] = idx;
            vqs[g] = (1.25f/128.f) * d * imask[msh[g]];
        } else {
            vqs[g] = 0.f;
        }
    }
    __syncthreads();
    if (tid == 0){
        float s = 0.f;
        #pragma unroll
        for (int g=0; g<16; g++) s += vqs[g];
        g_vqpart[blk] = s;
    }
}

// ---------------- decode ----------------
__global__ void __launch_bounds__(256) dec_kernel(const float* __restrict__ cb,
                                                  const float* __restrict__ d1b,
                                                  const float* __restrict__ d2b,
                                                  const float* __restrict__ d3b){
    __shared__ float v[128];
    __shared__ float h2[256];
    __shared__ float h3[256];
    const int e = blockIdx.x, tid = threadIdx.x;
    if (tid < 128) v[tid] = (e < 512) ? cb[e*128 + tid] : 0.f;
    __syncthreads();
    float a0=0.f,a1=0.f,a2=0.f,a3=0.f;
    #pragma unroll 4
    for (int k=0;k<128;k+=4){
        a0 = fmaf(g_d1T[(k+0)*256 + tid], v[k+0], a0);
        a1 = fmaf(g_d1T[(k+1)*256 + tid], v[k+1], a1);
        a2 = fmaf(g_d1T[(k+2)*256 + tid], v[k+2], a2);
        a3 = fmaf(g_d1T[(k+3)*256 + tid], v[k+3], a3);
    }
    h2[tid] = fmaxf(d1b[tid] + ((a0+a1)+(a2+a3)), 0.f);
    __syncthreads();
    a0=a1=a2=a3=0.f;
    #pragma unroll 4
    for (int k=0;k<256;k+=4){
        a0 = fmaf(g_d2T[(k+0)*256 + tid], h2[k+0], a0);
        a1 = fmaf(g_d2T[(k+1)*256 + tid], h2[k+1], a1);
        a2 = fmaf(g_d2T[(k+2)*256 + tid], h2[k+2], a2);
        a3 = fmaf(g_d2T[(k+3)*256 + tid], h2[k+3], a3);
    }
    h3[tid] = fmaxf(d2b[tid] + ((a0+a1)+(a2+a3)), 0.f);
    __syncthreads();
    if (tid < 100){
        a0=a1=a2=a3=0.f;
        #pragma unroll 4
        for (int k=0;k<256;k+=4){
            a0 = fmaf(g_d3T[(k+0)*100 + tid], h3[k+0], a0);
            a1 = fmaf(g_d3T[(k+1)*100 + tid], h3[k+1], a1);
            a2 = fmaf(g_d3T[(k+2)*100 + tid], h3[k+2], a2);
            a3 = fmaf(g_d3T[(k+3)*100 + tid], h3[k+3], a3);
        }
        g_decoded[e*100 + tid] = d3b[tid] + ((a0+a1)+(a2+a3));
    }
}

// ---------------- gather + masked-MSE partials ----------------
__global__ void __launch_bounds__(256) out_kernel(const float* __restrict__ x,
                                                  const float* __restrict__ traj,
                                                  const float* __restrict__ imask,
                                                  float* __restrict__ out, int full){
    __shared__ float swd[8], sww[8], sim[8];
    const int tid = threadIdx.x, wid = tid >> 5, lane = tid & 31;
    const int m = blockIdx.x*8 + wid;
    const float im = imask[m];
    const int sel = (im > 0.f) ? g_idx[m] : 512;
    const float* dec = g_decoded + sel*100;
    float sdw = 0.f, sw = 0.f;
    for (int t=lane; t<100; t+=32){
        float xh = dec[t];
        float xv = x[m*100 + t];
        float w  = im * traj[m*100 + t];
        out[m*100 + t] = xh;
        float df = xh - xv;
        sdw = fmaf(df*df, w, sdw);
        sw += w;
    }
    #pragma unroll
    for (int o=16;o;o>>=1){
        sdw += __shfl_down_sync(0xFFFFFFFFu, sdw, o);
        sw  += __shfl_down_sync(0xFFFFFFFFu, sw,  o);
    }
    if (lane == 0){
        swd[wid] = sdw; sww[wid] = sw; sim[wid] = im;
        if (full) out[OFF_IDX + m] = (im > 0.f) ? (float)g_idx[m] : -1.0f;
    }
    __syncthreads();
    if (tid == 0){
        float a=0.f,b=0.f,c=0.f;
        #pragma unroll
        for (int w2=0; w2<8; w2++){ a += swd[w2]; b += sww[w2]; c += sim[w2]; }
        g_rpart[blockIdx.x*3 + 0] = a;
        g_rpart[blockIdx.x*3 + 1] = b;
        g_rpart[blockIdx.x*3 + 2] = c;
    }
}

// ---------------- finalize ----------------
__global__ void fin_kernel(float* __restrict__ out, int full){
    __shared__ float sd[256], sw[256], si[256], sv[256];
    const int tid = threadIdx.x;
    float a=0.f,b=0.f,c=0.f,v=0.f;
    for (int i=tid; i<6400; i+=256){
        a += g_rpart[i*3 + 0];
        b += g_rpart[i*3 + 1];
        c += g_rpart[i*3 + 2];
    }
    for (int i=tid; i<3200; i+=256) v += g_vqpart[i];
    sd[tid]=a; sw[tid]=b; si[tid]=c; sv[tid]=v;
    __syncthreads();
    for (int o=128;o;o>>=1){
        if (tid < o){ sd[tid]+=sd[tid+o]; sw[tid]+=sw[tid+o]; si[tid]+=si[tid+o]; sv[tid]+=sv[tid+o]; }
        __syncthreads();
    }
    if (tid == 0 && full){
        out[OFF_RECON] = sd[0] / fmaxf(sw[0], 1.f);
        out[OFF_VQ]    = sv[0] / fmaxf(si[0], 1.f);
    }
}

// ---------------- launch ----------------
extern "C" void kernel_launch(void* const* d_in, const int* in_sizes, int n_in,
                              void* d_out, int out_size){
    const float* x    = (const float*)d_in[0];
    const float* traj = (const float*)d_in[1];
    const float* im   = (const float*)d_in[2];
    const float* c1w  = (const float*)d_in[3];
    const float* c1b  = (const float*)d_in[4];
    const float* c2w  = (const float*)d_in[5];
    const float* c2b  = (const float*)d_in[6];
    const float* latw = (const float*)d_in[7];
    const float* latb = (const float*)d_in[8];
    const float* cb   = (const float*)d_in[9];
    const float* d1w  = (const float*)d_in[10];
    const float* d1b  = (const float*)d_in[11];
    const float* d2w  = (const float*)d_in[12];
    const float* d2b  = (const float*)d_in[13];
    const float* d3w  = (const float*)d_in[14];
    const float* d3b  = (const float*)d_in[15];
    float* out = (float*)d_out;
    const int full = (out_size >= OUT_FULL) ? 1 : 0;

    prep_kernel<<<132, 256>>>(c2w, latw, cb, d1w, d2w, d3w);
    compactA<<<50, 1024>>>(im);
    compactC<<<50, 1024>>>(im);
    enc_kernel<<<(Mm + NI - 1)/NI, 128>>>(x, traj, im, c1w, c1b, c2b, latb);
    vq_kernel<<<Mm/16, 512>>>(im);
    dec_kernel<<<513, 256>>>(cb, d1b, d2b, d3b);
    out_kernel<<<Mm/8, 256>>>(x, traj, im, out, full);
    fin_kernel<<<1, 256>>>(out, full);
}

// round 14
// speedup vs baseline: 1.0903x; 1.0903x over previous
#include <cuda_runtime.h>
#include <cuda_bf16.h>
#include <cstdint>

// ---------------- problem constants ----------------
#define Bb 512
#define Nn 100
#define Tt 100
#define Mm (Bb*Nn)            // 51200
#define OFF_RECON  (Mm*Tt)
#define OFF_VQ     (Mm*Tt + 1)
#define OFF_IDX    (Mm*Tt + 2)
#define OUT_FULL   (Mm*Tt + 2 + Mm)

typedef unsigned long long u64;

// ---------------- scratch ----------------
__device__ __align__(16) float g_z[Mm*128];
__device__ int   g_idx[Mm];
__device__ __align__(16) float4 g_w4a[64*32];        // [ic][lane] = {w0A,w0B,w1A,w1B}
__device__ __align__(16) float2 g_w4b[64*32];        // [ic][lane] = {w2A,w2B}
__device__ __align__(16) float g_latT[64*128];
__device__ __align__(16) float g_cbP[512*128];
__device__ float g_cbnorm[512];
__device__ __align__(16) float g_d1T[128*256];
__device__ __align__(16) float g_d2T[256*256];
__device__ __align__(16) float g_d3T[256*100];
__device__ float g_decoded[513*100];
__device__ float g_vqpart[3200];
__device__ float g_rpart[6400*3];
__device__ int g_bcnt[50];
__device__ int g_cidx[Mm];
__device__ int g_nact;
__device__ int g_done;

// ---------------- f32x2 helpers ----------------
__device__ __forceinline__ u64 pack2(float a, float b){
    u64 r; asm("mov.b64 %0, {%1,%2};" : "=l"(r) : "f"(a), "f"(b)); return r;
}
__device__ __forceinline__ void ffma2(u64 &d, u64 a, u64 b){
    asm("fma.rn.f32x2 %0, %1, %2, %0;" : "+l"(d) : "l"(a), "l"(b));
}
__device__ __forceinline__ float2 unpack2(u64 v){
    float2 f; asm("mov.b64 {%0,%1}, %2;" : "=f"(f.x), "=f"(f.y) : "l"(v)); return f;
}

// ---------------- prep ----------------
__global__ void prep_kernel(const float* __restrict__ c2w, const float* __restrict__ latw,
                            const float* __restrict__ cb,  const float* __restrict__ d1w,
                            const float* __restrict__ d2w, const float* __restrict__ d3w){
    int gt = blockIdx.x*blockDim.x + threadIdx.x;
    int nt = gridDim.x*blockDim.x;
    if (gt == 0) g_done = 0;                 // reset last-block counter each launch
    for (int i=gt; i<64*32; i+=nt){
        int lane = i & 31; int ic = i >> 5;
        g_w4a[i] = make_float4(c2w[lane*192 + ic*3 + 0], c2w[(lane+32)*192 + ic*3 + 0],
                               c2w[lane*192 + ic*3 + 1], c2w[(lane+32)*192 + ic*3 + 1]);
        g_w4b[i] = make_float2(c2w[lane*192 + ic*3 + 2], c2w[(lane+32)*192 + ic*3 + 2]);
    }
    for (int i=gt; i<64*128; i+=nt){
        int e = i & 127; int oc = i >> 7;
        g_latT[i] = latw[e*64 + oc];
    }
    for (int i=gt; i<512*128; i+=nt){
        int j = i & 3; int r = i >> 2; int e = r & 511; int d4 = r >> 9;
        g_cbP[i] = cb[e*128 + d4*4 + j];
    }
    for (int e=gt; e<512; e+=nt){
        float s = 0.f;
        for (int d=0; d<128; d++){ float v = cb[e*128+d]; s = fmaf(v,v,s); }
        g_cbnorm[e] = s;
    }
    for (int i=gt; i<128*256; i+=nt){ int j=i&255; int k=i>>8; g_d1T[i] = d1w[j*128+k]; }
    for (int i=gt; i<256*256; i+=nt){ int j=i&255; int k=i>>8; g_d2T[i] = d2w[j*256+k]; }
    for (int i=gt; i<256*100; i+=nt){ int j=i%100; int k=i/100; g_d3T[i] = d3w[j*256+k]; }
}

// ---------------- compaction ----------------
__global__ void __launch_bounds__(1024) compactA(const float* __restrict__ imask){
    __shared__ int wc[32];
    const int tid = threadIdx.x;
    const int m = blockIdx.x*1024 + tid;
    unsigned b = __ballot_sync(0xFFFFFFFFu, imask[m] != 0.f);
    if ((tid & 31) == 0) wc[tid>>5] = __popc(b);
    __syncthreads();
    if (tid == 0){
        int s = 0;
        #pragma unroll
        for (int i=0;i<32;i++) s += wc[i];
        g_bcnt[blockIdx.x] = s;
    }
}

__global__ void __launch_bounds__(1024) compactC(const float* __restrict__ imask){
    __shared__ int woff[32];
    __shared__ int sbase;
    const int tid = threadIdx.x;
    const int bid = blockIdx.x;
    const int m = bid*1024 + tid;
    const bool act = imask[m] != 0.f;
    unsigned b = __ballot_sync(0xFFFFFFFFu, act);
    if ((tid & 31) == 0) woff[tid>>5] = __popc(b);
    __syncthreads();
    if (tid == 0){
        int base = 0;
        for (int i=0;i<bid;i++) base += g_bcnt[i];
        sbase = base;
        int run = 0;
        #pragma unroll
        for (int w=0;w<32;w++){ int c = woff[w]; woff[w] = run; run += c; }
        if (bid == 0){
            int tot = 0;
            #pragma unroll
            for (int i=0;i<50;i++) tot += g_bcnt[i];
            g_nact = tot;
        }
    }
    __syncthreads();
    if (act){
        int rank = __popc(b & ((1u << (tid & 31)) - 1u));
        g_cidx[sbase + woff[tid>>5] + rank] = m;
    }
}

// ---------------- encoder (R12 inner loops) + decode in spare blocks ----------------
#define HROW 52   // mod 4 == 0 -> 16B-aligned rows; gcd(52,32)=4
// shh: h[l] at q=l (q in [0,49]); shs: h[l] at q=l+1, pads q=0 (h[-1]=0), q=51 (h[50]=0)

template<int NP>
__device__ __forceinline__ void conv2_tile(int lane, int l0, u64 bbA, u64 bbB,
                                           const float* __restrict__ shh,
                                           const float* __restrict__ shs,
                                           float &outA, float &outB){
    constexpr int NK = NP/2;
    u64 accA[NP], accB[NP];
    #pragma unroll
    for (int p=0;p<NP;p++){ accA[p]=bbA; accB[p]=bbB; }
    #pragma unroll 2
    for (int ic=0; ic<64; ic++){
        float4 w01 = g_w4a[ic*32 + lane];
        float2 w2  = g_w4b[ic*32 + lane];
        u64 W0a = pack2(w01.x,w01.x), W0b = pack2(w01.y,w01.y);
        u64 W1a = pack2(w01.z,w01.z), W1b = pack2(w01.w,w01.w);
        u64 W2a = pack2(w2.x,w2.x),   W2b = pack2(w2.y,w2.y);
        const float* hr = shh + ic*HROW + l0;
        const float* sr = shs + ic*HROW + l0;
        ulonglong2 Sc = *(const ulonglong2*)(sr);
        #pragma unroll
        for (int k=0;k<NK;k++){
            ulonglong2 A2 = *(const ulonglong2*)(hr + 4*k);
            ulonglong2 Sn = *(const ulonglong2*)(sr + 4*k + 4);
            const int p = 2*k;
            ffma2(accA[p], W0a, Sc.x); ffma2(accB[p], W0b, Sc.x);
            ffma2(accA[p], W1a, A2.x); ffma2(accB[p], W1b, A2.x);
            ffma2(accA[p], W2a, Sc.y); ffma2(accB[p], W2b, Sc.y);
            ffma2(accA[p+1], W0a, Sc.y); ffma2(accB[p+1], W0b, Sc.y);
            ffma2(accA[p+1], W1a, A2.y); ffma2(accB[p+1], W1b, A2.y);
            ffma2(accA[p+1], W2a, Sn.x); ffma2(accB[p+1], W2b, Sn.x);
            Sc = Sn;
        }
        if (NP & 1){
            const int p = NP - 1;
            u64 Atl = *(const u64*)(hr + 2*p);
            ffma2(accA[p], W0a, Sc.x); ffma2(accB[p], W0b, Sc.x);
            ffma2(accA[p], W1a, Atl);  ffma2(accB[p], W1b, Atl);
            ffma2(accA[p], W2a, Sc.y); ffma2(accB[p], W2b, Sc.y);
        }
    }
    float sA = 0.f, sB = 0.f;
    #pragma unroll
    for (int p=0;p<NP;p++){
        float2 fa = unpack2(accA[p]);
        float2 fb = unpack2(accB[p]);
        sA += fmaxf(fa.x,0.f) + fmaxf(fa.y,0.f);
        sB += fmaxf(fb.x,0.f) + fmaxf(fb.y,0.f);
    }
    outA = sA; outB = sB;
}

__global__ void __launch_bounds__(128) enc_kernel(const float* __restrict__ x,
                                                  const float* __restrict__ traj,
                                                  const float* __restrict__ imask,
                                                  const float* __restrict__ c1w,
                                                  const float* __restrict__ c1b,
                                                  const float* __restrict__ c2b,
                                                  const float* __restrict__ latb,
                                                  const float* __restrict__ cb,
                                                  const float* __restrict__ d1b,
                                                  const float* __restrict__ d2b,
                                                  const float* __restrict__ d3b){
    __shared__ __align__(16) float xs[112];
    __shared__ __align__(16) float shh[64*HROW];
    __shared__ __align__(16) float shs[64*HROW];
    float* phmA = shh;          // aliased (dead after conv2)
    float* hmsA = shh + 256;
    const int tid = threadIdx.x;
    const int nact = g_nact;
    const int s = blockIdx.x;

    if (s >= nact){
        // ---- decoder path on spare blocks: e = s - nact in [0, 512] ----
        const int e = s - nact;
        if (e >= 513) return;
        float* dv  = shh;          // 128
        float* dh2 = shh + 128;    // 256
        float* dh3 = shh + 384;    // 256
        dv[tid & 127] = 0.f;       // covers both halves writing same region? no:
        // (128 threads: each writes its own slot)
        if (e < 512) dv[tid] = cb[e*128 + tid];
        else         dv[tid] = 0.f;
        __syncthreads();
        #pragma unroll
        for (int jj=0; jj<2; jj++){
            const int j = tid + jj*128;
            float a0=0.f,a1=0.f,a2=0.f,a3=0.f;
            #pragma unroll 4
            for (int k=0;k<128;k+=4){
                a0 = fmaf(g_d1T[(k+0)*256 + j], dv[k+0], a0);
                a1 = fmaf(g_d1T[(k+1)*256 + j], dv[k+1], a1);
                a2 = fmaf(g_d1T[(k+2)*256 + j], dv[k+2], a2);
                a3 = fmaf(g_d1T[(k+3)*256 + j], dv[k+3], a3);
            }
            dh2[j] = fmaxf(d1b[j] + ((a0+a1)+(a2+a3)), 0.f);
        }
        __syncthreads();
        #pragma unroll
        for (int jj=0; jj<2; jj++){
            const int j = tid + jj*128;
            float a0=0.f,a1=0.f,a2=0.f,a3=0.f;
            #pragma unroll 4
            for (int k=0;k<256;k+=4){
                a0 = fmaf(g_d2T[(k+0)*256 + j], dh2[k+0], a0);
                a1 = fmaf(g_d2T[(k+1)*256 + j], dh2[k+1], a1);
                a2 = fmaf(g_d2T[(k+2)*256 + j], dh2[k+2], a2);
                a3 = fmaf(g_d2T[(k+3)*256 + j], dh2[k+3], a3);
            }
            dh3[j] = fmaxf(d2b[j] + ((a0+a1)+(a2+a3)), 0.f);
        }
        __syncthreads();
        if (tid < 100){
            float a0=0.f,a1=0.f,a2=0.f,a3=0.f;
            #pragma unroll 4
            for (int k=0;k<256;k+=4){
                a0 = fmaf(g_d3T[(k+0)*100 + tid], dh3[k+0], a0);
                a1 = fmaf(g_d3T[(k+1)*100 + tid], dh3[k+1], a1);
                a2 = fmaf(g_d3T[(k+2)*100 + tid], dh3[k+2], a2);
                a3 = fmaf(g_d3T[(k+3)*100 + tid], dh3[k+3], a3);
            }
            g_decoded[e*100 + tid] = d3b[tid] + ((a0+a1)+(a2+a3));
        }
        return;
    }

    // ---- encoder path (R12, unchanged) ----
    const int m = g_cidx[s];
    const float im = imask[m];

    const int oc = tid & 63, half = tid >> 6;
    if (tid < 112){
        float v = 0.f;
        if (tid >= 2 && tid < 102) v = x[m*100 + tid - 2] * traj[m*100 + tid - 2] * im;
        xs[tid] = v;
    }
    {
        int r = tid >> 1;
        int q = (tid & 1) ? 51 : 0;
        shs[r*HROW + q] = 0.f;
    }

    float w1r[6];
    #pragma unroll
    for (int j=0;j<6;j++) w1r[j] = c1w[oc*6 + (j&1)*3 + (j>>1)];
    const float b1v = c1b[oc];
    __syncthreads();

    {
        const int ls = half ? 26 : 0, le = half ? 50 : 26;
        float* dh = shh + oc*HROW;
        float* ds = shs + oc*HROW + 1;
        float2 p0 = *(const float2*)(xs + 2*ls);
        float2 p1 = *(const float2*)(xs + 2*ls + 2);
        float2 p2 = *(const float2*)(xs + 2*ls + 4);
        #pragma unroll 2
        for (int l=ls; l<le; l++){
            float a = b1v;
            a = fmaf(w1r[0], p0.x, a);
            a = fmaf(w1r[1], p0.y, a);
            a = fmaf(w1r[2], p1.x, a);
            a = fmaf(w1r[3], p1.y, a);
            a = fmaf(w1r[4], p2.x, a);
            a = fmaf(w1r[5], p2.y, a);
            a = fmaxf(a, 0.f);
            dh[l] = a;
            ds[l] = a;
            p0 = p1; p1 = p2;
            if (l+1 < le) p2 = *(const float2*)(xs + 2*(l+1) + 4);
        }
    }
    __syncthreads();

    const int wid = tid >> 5, lane = tid & 31;
    const float bA = c2b[lane], bB = c2b[lane+32];
    const u64 bbA = pack2(bA,bA), bbB = pack2(bB,bB);
    float sA, sB;
    if      (wid == 0) conv2_tile<6>(lane, 0,  bbA, bbB, shh, shs, sA, sB);
    else if (wid == 1) conv2_tile<6>(lane, 12, bbA, bbB, shh, shs, sA, sB);
    else if (wid == 2) conv2_tile<6>(lane, 24, bbA, bbB, shh, shs, sA, sB);
    else               conv2_tile<7>(lane, 36, bbA, bbB, shh, shs, sA, sB);
    __syncthreads();
    phmA[wid*64 + lane]      = sA;
    phmA[wid*64 + lane + 32] = sB;
    __syncthreads();
    if (tid < 64)
        hmsA[tid] = (((phmA[tid] + phmA[64 + tid]) + phmA[128 + tid]) + phmA[192 + tid]) * (1.f/50.f);
    __syncthreads();

    float acc = latb[tid];
    #pragma unroll 4
    for (int o2=0; o2<64; o2++) acc = fmaf(g_latT[o2*128 + tid], hmsA[o2], acc);
    g_z[m*128 + tid] = acc * im;
}

// ---------------- VQ (unchanged; reference-matched rounding) ----------------
__global__ void __launch_bounds__(512) vq_kernel(const float* __restrict__ imask){
    __shared__ __align__(16) float zsh[16*128];
    __shared__ u64 smin[16];
    __shared__ float znorm[16];
    __shared__ float vqs[16];
    __shared__ int msh[16];
    __shared__ int vld[16];
    const int tid = threadIdx.x;
    const int blk = blockIdx.x;
    const int nact = g_nact;
    const int s0 = blk * 16;
    if (s0 >= nact){
        if (tid == 0) g_vqpart[blk] = 0.f;
        return;
    }
    if (tid < 16){
        int s = s0 + tid;
        int valid = (s < nact);
        msh[tid] = valid ? g_cidx[s] : g_cidx[0];
        vld[tid] = valid;
        smin[tid] = ~0ULL;
    }
    __syncthreads();
    for (int i=tid; i<2048; i+=512){
        int m = msh[i >> 7];
        zsh[i] = 2.0f * g_z[m*128 + (i & 127)];
    }
    __syncthreads();

    const int wid = tid >> 5, lane = tid & 31;
    {
        float s = 0.f;
        #pragma unroll
        for (int d=lane; d<128; d+=32){ float v = zsh[wid*128 + d]; s = fmaf(v,v,s); }
        #pragma unroll
        for (int o=16;o;o>>=1) s += __shfl_down_sync(0xFFFFFFFFu, s, o);
        if (lane == 0) znorm[wid] = 0.25f * s;
    }
    __syncthreads();

    const int e = tid;
    u64 acc[16];
    #pragma unroll
    for (int g=0; g<16; g++) acc[g] = 0ULL;
    #pragma unroll 1
    for (int d4=0; d4<32; d4++){
        ulonglong2 cbp = *(const ulonglong2*)(g_cbP + (d4*512 + e)*4);
        #pragma unroll
        for (int g=0; g<16; g++){
            ulonglong2 zz = *(const ulonglong2*)(zsh + g*128 + d4*4);
            ffma2(acc[g], cbp.x, zz.x);
            ffma2(acc[g], cbp.y, zz.y);
        }
    }
    const float cbn = g_cbnorm[e];
    #pragma unroll
    for (int g=0; g<16; g++){
        float2 a = unpack2(acc[g]);
        float dot2 = a.x + a.y;
        float t1 = znorm[g] - dot2;
        float d  = t1 + cbn;
        unsigned u = __float_as_uint(d);
        unsigned mono = (u & 0x80000000u) ? ~u : (u | 0x80000000u);
        u64 key = ((u64)mono << 32) | (unsigned)e;
        #pragma unroll
        for (int o=16;o;o>>=1){
            u64 other = __shfl_down_sync(0xFFFFFFFFu, key, o);
            key = (other < key) ? other : key;
        }
        if (lane == 0) atomicMin(&smin[g], key);
    }
    __syncthreads();
    if (tid < 16){
        const int g = tid;
        u64 key = smin[g];
        unsigned mono = (unsigned)(key >> 32);
        unsigned u = (mono & 0x80000000u) ? (mono ^ 0x80000000u) : ~mono;
        float d = __uint_as_float(u);
        int idx = (int)(key & 0xFFFFFFFFu);
        if (vld[g]){
            g_idx[msh[g]] = idx;
            vqs[g] = (1.25f/128.f) * d * imask[msh[g]];
        } else {
            vqs[g] = 0.f;
        }
    }
    __syncthreads();
    if (tid == 0){
        float s = 0.f;
        #pragma unroll
        for (int g=0; g<16; g++) s += vqs[g];
        g_vqpart[blk] = s;
    }
}

// ---------------- gather + masked-MSE partials + folded finalize ----------------
__global__ void __launch_bounds__(256) out_kernel(const float* __restrict__ x,
                                                  const float* __restrict__ traj,
                                                  const float* __restrict__ imask,
                                                  float* __restrict__ out, int full){
    __shared__ float swd[8], sww[8], sim[8];
    __shared__ int slast;
    const int tid = threadIdx.x, wid = tid >> 5, lane = tid & 31;
    const int m = blockIdx.x*8 + wid;
    const float im = imask[m];
    const int sel = (im > 0.f) ? g_idx[m] : 512;
    const float* dec = g_decoded + sel*100;
    float sdw = 0.f, sw = 0.f;
    for (int t=lane; t<100; t+=32){
        float xh = dec[t];
        float xv = x[m*100 + t];
        float w  = im * traj[m*100 + t];
        out[m*100 + t] = xh;
        float df = xh - xv;
        sdw = fmaf(df*df, w, sdw);
        sw += w;
    }
    #pragma unroll
    for (int o=16;o;o>>=1){
        sdw += __shfl_down_sync(0xFFFFFFFFu, sdw, o);
        sw  += __shfl_down_sync(0xFFFFFFFFu, sw,  o);
    }
    if (lane == 0){
        swd[wid] = sdw; sww[wid] = sw; sim[wid] = im;
        if (full) out[OFF_IDX + m] = (im > 0.f) ? (float)g_idx[m] : -1.0f;
    }
    __syncthreads();
    if (tid == 0){
        float a=0.f,b=0.f,c=0.f;
        #pragma unroll
        for (int w2=0; w2<8; w2++){ a += swd[w2]; b += sww[w2]; c += sim[w2]; }
        g_rpart[blockIdx.x*3 + 0] = a;
        g_rpart[blockIdx.x*3 + 1] = b;
        g_rpart[blockIdx.x*3 + 2] = c;
        __threadfence();
        int t = atomicAdd(&g_done, 1);
        slast = (t == (int)gridDim.x - 1);
    }
    __syncthreads();
    if (!slast) return;

    // ---- folded finalize (deterministic: one block, fixed order) ----
    __shared__ float sd[256], sw2[256], si[256], sv[256];
    float a=0.f,b=0.f,c=0.f,v=0.f;
    for (int i=tid; i<6400; i+=256){
        a += __ldcg(&g_rpart[i*3 + 0]);
        b += __ldcg(&g_rpart[i*3 + 1]);
        c += __ldcg(&g_rpart[i*3 + 2]);
    }
    for (int i=tid; i<3200; i+=256) v += __ldcg(&g_vqpart[i]);
    sd[tid]=a; sw2[tid]=b; si[tid]=c; sv[tid]=v;
    __syncthreads();
    for (int o=128;o;o>>=1){
        if (tid < o){ sd[tid]+=sd[tid+o]; sw2[tid]+=sw2[tid+o]; si[tid]+=si[tid+o]; sv[tid]+=sv[tid+o]; }
        __syncthreads();
    }
    if (tid == 0 && full){
        out[OFF_RECON] = sd[0] / fmaxf(sw2[0], 1.f);
        out[OFF_VQ]    = sv[0] / fmaxf(si[0], 1.f);
    }
}

// ---------------- launch ----------------
extern "C" void kernel_launch(void* const* d_in, const int* in_sizes, int n_in,
                              void* d_out, int out_size){
    const float* x    = (const float*)d_in[0];
    const float* traj = (const float*)d_in[1];
    const float* im   = (const float*)d_in[2];
    const float* c1w  = (const float*)d_in[3];
    const float* c1b  = (const float*)d_in[4];
    const float* c2w  = (const float*)d_in[5];
    const float* c2b  = (const float*)d_in[6];
    const float* latw = (const float*)d_in[7];
    const float* latb = (const float*)d_in[8];
    const float* cb   = (const float*)d_in[9];
    const float* d1w  = (const float*)d_in[10];
    const float* d1b  = (const float*)d_in[11];
    const float* d2w  = (const float*)d_in[12];
    const float* d2b  = (const float*)d_in[13];
    const float* d3w  = (const float*)d_in[14];
    const float* d3b  = (const float*)d_in[15];
    float* out = (float*)d_out;
    const int full = (out_size >= OUT_FULL) ? 1 : 0;

    prep_kernel<<<132, 256>>>(c2w, latw, cb, d1w, d2w, d3w);
    compactA<<<50, 1024>>>(im);
    compactC<<<50, 1024>>>(im);
    enc_kernel<<<Mm + 513, 128>>>(x, traj, im, c1w, c1b, c2b, latb, cb, d1b, d2b, d3b);
    vq_kernel<<<Mm/16, 512>>>(im);
    out_kernel<<<Mm/8, 256>>>(x, traj, im, out, full);
}

// round 15
// speedup vs baseline: 1.1076x; 1.0159x over previous
#include <cuda_runtime.h>
#include <cuda_bf16.h>
#include <cstdint>

// ---------------- problem constants ----------------
#define Bb 512
#define Nn 100
#define Tt 100
#define Mm (Bb*Nn)            // 51200
#define OFF_RECON  (Mm*Tt)
#define OFF_VQ     (Mm*Tt + 1)
#define OFF_IDX    (Mm*Tt + 2)
#define OUT_FULL   (Mm*Tt + 2 + Mm)

typedef unsigned long long u64;

// ---------------- scratch ----------------
__device__ __align__(16) float g_z[Mm*128];
__device__ int   g_idx[Mm];
__device__ __align__(16) float4 g_w4a[64*32];        // [ic][lane] = {w0A,w0B,w1A,w1B}
__device__ __align__(16) float2 g_w4b[64*32];        // [ic][lane] = {w2A,w2B}
__device__ __align__(16) float g_latT[64*128];
__device__ __align__(16) float g_cbP[512*128];
__device__ float g_cbnorm[512];
__device__ __align__(16) float g_d1T[128*256];
__device__ __align__(16) float g_d2T[256*256];
__device__ __align__(16) float g_d3T[256*100];
__device__ float g_decoded[513*100];
__device__ float g_vqpart[3200];
__device__ float g_rpart[6400*3];
__device__ int g_bcnt[50];
__device__ int g_cidx[Mm];
__device__ int g_nact;
__device__ int g_done;

// ---------------- f32x2 helpers ----------------
__device__ __forceinline__ u64 pack2(float a, float b){
    u64 r; asm("mov.b64 %0, {%1,%2};" : "=l"(r) : "f"(a), "f"(b)); return r;
}
__device__ __forceinline__ void ffma2(u64 &d, u64 a, u64 b){
    asm("fma.rn.f32x2 %0, %1, %2, %0;" : "+l"(d) : "l"(a), "l"(b));
}
__device__ __forceinline__ float2 unpack2(u64 v){
    float2 f; asm("mov.b64 {%0,%1}, %2;" : "=f"(f.x), "=f"(f.y) : "l"(v)); return f;
}

// ---------------- prep (+ folded compactA: blocks 0..49 count their chunk) ----------------
__global__ void prep_kernel(const float* __restrict__ c2w, const float* __restrict__ latw,
                            const float* __restrict__ cb,  const float* __restrict__ d1w,
                            const float* __restrict__ d2w, const float* __restrict__ d3w,
                            const float* __restrict__ imask){
    __shared__ int wc[8];
    int gt = blockIdx.x*blockDim.x + threadIdx.x;
    int nt = gridDim.x*blockDim.x;
    if (gt == 0) g_done = 0;
    // folded compactA: block b < 50 counts actives in imask[b*1024 .. b*1024+1023]
    if (blockIdx.x < 50){
        const int tid = threadIdx.x;
        int cnt = 0;
        #pragma unroll
        for (int j=0;j<4;j++){
            int m = blockIdx.x*1024 + j*256 + tid;
            unsigned b = __ballot_sync(0xFFFFFFFFu, imask[m] != 0.f);
            if ((tid & 31) == 0) cnt += __popc(b);
        }
        if ((tid & 31) == 0) wc[tid>>5] = 0;
        __syncthreads();
        if ((tid & 31) == 0) atomicAdd(&wc[tid>>5], cnt);
        __syncthreads();
        if (tid == 0){
            int s = 0;
            #pragma unroll
            for (int i=0;i<8;i++) s += wc[i];
            g_bcnt[blockIdx.x] = s;
        }
    }
    for (int i=gt; i<64*32; i+=nt){
        int lane = i & 31; int ic = i >> 5;
        g_w4a[i] = make_float4(c2w[lane*192 + ic*3 + 0], c2w[(lane+32)*192 + ic*3 + 0],
                               c2w[lane*192 + ic*3 + 1], c2w[(lane+32)*192 + ic*3 + 1]);
        g_w4b[i] = make_float2(c2w[lane*192 + ic*3 + 2], c2w[(lane+32)*192 + ic*3 + 2]);
    }
    for (int i=gt; i<64*128; i+=nt){
        int e = i & 127; int oc = i >> 7;
        g_latT[i] = latw[e*64 + oc];
    }
    for (int i=gt; i<512*128; i+=nt){
        int j = i & 3; int r = i >> 2; int e = r & 511; int d4 = r >> 9;
        g_cbP[i] = cb[e*128 + d4*4 + j];
    }
    for (int e=gt; e<512; e+=nt){
        float s = 0.f;
        for (int d=0; d<128; d++){ float v = cb[e*128+d]; s = fmaf(v,v,s); }
        g_cbnorm[e] = s;
    }
    for (int i=gt; i<128*256; i+=nt){ int j=i&255; int k=i>>8; g_d1T[i] = d1w[j*128+k]; }
    for (int i=gt; i<256*256; i+=nt){ int j=i&255; int k=i>>8; g_d2T[i] = d2w[j*256+k]; }
    for (int i=gt; i<256*100; i+=nt){ int j=i%100; int k=i/100; g_d3T[i] = d3w[j*256+k]; }
}

// ---------------- compaction scatter (needs all g_bcnt) ----------------
__global__ void __launch_bounds__(1024) compactC(const float* __restrict__ imask){
    __shared__ int woff[32];
    __shared__ int sbase;
    const int tid = threadIdx.x;
    const int bid = blockIdx.x;
    const int m = bid*1024 + tid;
    const bool act = imask[m] != 0.f;
    unsigned b = __ballot_sync(0xFFFFFFFFu, act);
    if ((tid & 31) == 0) woff[tid>>5] = __popc(b);
    __syncthreads();
    if (tid == 0){
        int base = 0;
        for (int i=0;i<bid;i++) base += g_bcnt[i];
        sbase = base;
        int run = 0;
        #pragma unroll
        for (int w=0;w<32;w++){ int c = woff[w]; woff[w] = run; run += c; }
        if (bid == 0){
            int tot = 0;
            #pragma unroll
            for (int i=0;i<50;i++) tot += g_bcnt[i];
            g_nact = tot;
        }
    }
    __syncthreads();
    if (act){
        int rank = __popc(b & ((1u << (tid & 31)) - 1u));
        g_cidx[sbase + woff[tid>>5] + rank] = m;
    }
}

// ---------------- encoder (R12 inner loops, ic unroll 4) + decode in spare blocks ----------------
#define HROW 52   // mod 4 == 0 -> 16B-aligned rows; gcd(52,32)=4
// shh: h[l] at q=l (q in [0,49]); shs: h[l] at q=l+1, pads q=0 (h[-1]=0), q=51 (h[50]=0)

template<int NP>
__device__ __forceinline__ void conv2_tile(int lane, int l0, u64 bbA, u64 bbB,
                                           const float* __restrict__ shh,
                                           const float* __restrict__ shs,
                                           float &outA, float &outB){
    constexpr int NK = NP/2;
    u64 accA[NP], accB[NP];
    #pragma unroll
    for (int p=0;p<NP;p++){ accA[p]=bbA; accB[p]=bbB; }
    #pragma unroll 4
    for (int ic=0; ic<64; ic++){
        float4 w01 = g_w4a[ic*32 + lane];
        float2 w2  = g_w4b[ic*32 + lane];
        u64 W0a = pack2(w01.x,w01.x), W0b = pack2(w01.y,w01.y);
        u64 W1a = pack2(w01.z,w01.z), W1b = pack2(w01.w,w01.w);
        u64 W2a = pack2(w2.x,w2.x),   W2b = pack2(w2.y,w2.y);
        const float* hr = shh + ic*HROW + l0;
        const float* sr = shs + ic*HROW + l0;
        ulonglong2 Sc = *(const ulonglong2*)(sr);
        #pragma unroll
        for (int k=0;k<NK;k++){
            ulonglong2 A2 = *(const ulonglong2*)(hr + 4*k);
            ulonglong2 Sn = *(const ulonglong2*)(sr + 4*k + 4);
            const int p = 2*k;
            ffma2(accA[p], W0a, Sc.x); ffma2(accB[p], W0b, Sc.x);
            ffma2(accA[p], W1a, A2.x); ffma2(accB[p], W1b, A2.x);
            ffma2(accA[p], W2a, Sc.y); ffma2(accB[p], W2b, Sc.y);
            ffma2(accA[p+1], W0a, Sc.y); ffma2(accB[p+1], W0b, Sc.y);
            ffma2(accA[p+1], W1a, A2.y); ffma2(accB[p+1], W1b, A2.y);
            ffma2(accA[p+1], W2a, Sn.x); ffma2(accB[p+1], W2b, Sn.x);
            Sc = Sn;
        }
        if (NP & 1){
            const int p = NP - 1;
            u64 Atl = *(const u64*)(hr + 2*p);
            ffma2(accA[p], W0a, Sc.x); ffma2(accB[p], W0b, Sc.x);
            ffma2(accA[p], W1a, Atl);  ffma2(accB[p], W1b, Atl);
            ffma2(accA[p], W2a, Sc.y); ffma2(accB[p], W2b, Sc.y);
        }
    }
    float sA = 0.f, sB = 0.f;
    #pragma unroll
    for (int p=0;p<NP;p++){
        float2 fa = unpack2(accA[p]);
        float2 fb = unpack2(accB[p]);
        sA += fmaxf(fa.x,0.f) + fmaxf(fa.y,0.f);
        sB += fmaxf(fb.x,0.f) + fmaxf(fb.y,0.f);
    }
    outA = sA; outB = sB;
}

__global__ void __launch_bounds__(128) enc_kernel(const float* __restrict__ x,
                                                  const float* __restrict__ traj,
                                                  const float* __restrict__ imask,
                                                  const float* __restrict__ c1w,
                                                  const float* __restrict__ c1b,
                                                  const float* __restrict__ c2b,
                                                  const float* __restrict__ latb,
                                                  const float* __restrict__ cb,
                                                  const float* __restrict__ d1b,
                                                  const float* __restrict__ d2b,
                                                  const float* __restrict__ d3b){
    __shared__ __align__(16) float xs[112];
    __shared__ __align__(16) float shh[64*HROW];
    __shared__ __align__(16) float shs[64*HROW];
    float* phmA = shh;          // aliased (dead after conv2)
    float* hmsA = shh + 256;
    const int tid = threadIdx.x;
    const int nact = g_nact;
    const int s = blockIdx.x;

    if (s >= nact){
        // ---- decoder path on spare blocks: e = s - nact in [0, 512] ----
        const int e = s - nact;
        if (e >= 513) return;
        float* dv  = shh;          // 128
        float* dh2 = shh + 128;    // 256
        float* dh3 = shh + 384;    // 256
        dv[tid] = (e < 512) ? cb[e*128 + tid] : 0.f;
        __syncthreads();
        #pragma unroll
        for (int jj=0; jj<2; jj++){
            const int j = tid + jj*128;
            float a0=0.f,a1=0.f,a2=0.f,a3=0.f;
            #pragma unroll 4
            for (int k=0;k<128;k+=4){
                a0 = fmaf(g_d1T[(k+0)*256 + j], dv[k+0], a0);
                a1 = fmaf(g_d1T[(k+1)*256 + j], dv[k+1], a1);
                a2 = fmaf(g_d1T[(k+2)*256 + j], dv[k+2], a2);
                a3 = fmaf(g_d1T[(k+3)*256 + j], dv[k+3], a3);
            }
            dh2[j] = fmaxf(d1b[j] + ((a0+a1)+(a2+a3)), 0.f);
        }
        __syncthreads();
        #pragma unroll
        for (int jj=0; jj<2; jj++){
            const int j = tid + jj*128;
            float a0=0.f,a1=0.f,a2=0.f,a3=0.f;
            #pragma unroll 4
            for (int k=0;k<256;k+=4){
                a0 = fmaf(g_d2T[(k+0)*256 + j], dh2[k+0], a0);
                a1 = fmaf(g_d2T[(k+1)*256 + j], dh2[k+1], a1);
                a2 = fmaf(g_d2T[(k+2)*256 + j], dh2[k+2], a2);
                a3 = fmaf(g_d2T[(k+3)*256 + j], dh2[k+3], a3);
            }
            dh3[j] = fmaxf(d2b[j] + ((a0+a1)+(a2+a3)), 0.f);
        }
        __syncthreads();
        if (tid < 100){
            float a0=0.f,a1=0.f,a2=0.f,a3=0.f;
            #pragma unroll 4
            for (int k=0;k<256;k+=4){
                a0 = fmaf(g_d3T[(k+0)*100 + tid], dh3[k+0], a0);
                a1 = fmaf(g_d3T[(k+1)*100 + tid], dh3[k+1], a1);
                a2 = fmaf(g_d3T[(k+2)*100 + tid], dh3[k+2], a2);
                a3 = fmaf(g_d3T[(k+3)*100 + tid], dh3[k+3], a3);
            }
            g_decoded[e*100 + tid] = d3b[tid] + ((a0+a1)+(a2+a3));
        }
        return;
    }

    // ---- encoder path ----
    const int m = g_cidx[s];
    const float im = imask[m];

    const int oc = tid & 63, half = tid >> 6;
    if (tid < 112){
        float v = 0.f;
        if (tid >= 2 && tid < 102) v = x[m*100 + tid - 2] * traj[m*100 + tid - 2] * im;
        xs[tid] = v;
    }
    {
        int r = tid >> 1;
        int q = (tid & 1) ? 51 : 0;
        shs[r*HROW + q] = 0.f;
    }

    float w1r[6];
    #pragma unroll
    for (int j=0;j<6;j++) w1r[j] = c1w[oc*6 + (j&1)*3 + (j>>1)];
    const float b1v = c1b[oc];
    __syncthreads();

    {
        const int ls = half ? 26 : 0, le = half ? 50 : 26;
        float* dh = shh + oc*HROW;
        float* ds = shs + oc*HROW + 1;
        float2 p0 = *(const float2*)(xs + 2*ls);
        float2 p1 = *(const float2*)(xs + 2*ls + 2);
        float2 p2 = *(const float2*)(xs + 2*ls + 4);
        #pragma unroll 2
        for (int l=ls; l<le; l++){
            float a = b1v;
            a = fmaf(w1r[0], p0.x, a);
            a = fmaf(w1r[1], p0.y, a);
            a = fmaf(w1r[2], p1.x, a);
            a = fmaf(w1r[3], p1.y, a);
            a = fmaf(w1r[4], p2.x, a);
            a = fmaf(w1r[5], p2.y, a);
            a = fmaxf(a, 0.f);
            dh[l] = a;
            ds[l] = a;
            p0 = p1; p1 = p2;
            if (l+1 < le) p2 = *(const float2*)(xs + 2*(l+1) + 4);
        }
    }
    __syncthreads();

    const int wid = tid >> 5, lane = tid & 31;
    const float bA = c2b[lane], bB = c2b[lane+32];
    const u64 bbA = pack2(bA,bA), bbB = pack2(bB,bB);
    float sA, sB;
    if      (wid == 0) conv2_tile<6>(lane, 0,  bbA, bbB, shh, shs, sA, sB);
    else if (wid == 1) conv2_tile<6>(lane, 12, bbA, bbB, shh, shs, sA, sB);
    else if (wid == 2) conv2_tile<6>(lane, 24, bbA, bbB, shh, shs, sA, sB);
    else               conv2_tile<7>(lane, 36, bbA, bbB, shh, shs, sA, sB);
    __syncthreads();
    phmA[wid*64 + lane]      = sA;
    phmA[wid*64 + lane + 32] = sB;
    __syncthreads();
    if (tid < 64)
        hmsA[tid] = (((phmA[tid] + phmA[64 + tid]) + phmA[128 + tid]) + phmA[192 + tid]) * (1.f/50.f);
    __syncthreads();

    float acc = latb[tid];
    #pragma unroll 4
    for (int o2=0; o2<64; o2++) acc = fmaf(g_latT[o2*128 + tid], hmsA[o2], acc);
    g_z[m*128 + tid] = acc * im;
}

// ---------------- VQ (unchanged; reference-matched rounding) ----------------
__global__ void __launch_bounds__(512) vq_kernel(const float* __restrict__ imask){
    __shared__ __align__(16) float zsh[16*128];
    __shared__ u64 smin[16];
    __shared__ float znorm[16];
    __shared__ float vqs[16];
    __shared__ int msh[16];
    __shared__ int vld[16];
    const int tid = threadIdx.x;
    const int blk = blockIdx.x;
    const int nact = g_nact;
    const int s0 = blk * 16;
    if (s0 >= nact){
        if (tid == 0) g_vqpart[blk] = 0.f;
        return;
    }
    if (tid < 16){
        int s = s0 + tid;
        int valid = (s < nact);
        msh[tid] = valid ? g_cidx[s] : g_cidx[0];
        vld[tid] = valid;
        smin[tid] = ~0ULL;
    }
    __syncthreads();
    for (int i=tid; i<2048; i+=512){
        int m = msh[i >> 7];
        zsh[i] = 2.0f * g_z[m*128 + (i & 127)];
    }
    __syncthreads();

    const int wid = tid >> 5, lane = tid & 31;
    {
        float s = 0.f;
        #pragma unroll
        for (int d=lane; d<128; d+=32){ float v = zsh[wid*128 + d]; s = fmaf(v,v,s); }
        #pragma unroll
        for (int o=16;o;o>>=1) s += __shfl_down_sync(0xFFFFFFFFu, s, o);
        if (lane == 0) znorm[wid] = 0.25f * s;
    }
    __syncthreads();

    const int e = tid;
    u64 acc[16];
    #pragma unroll
    for (int g=0; g<16; g++) acc[g] = 0ULL;
    #pragma unroll 1
    for (int d4=0; d4<32; d4++){
        ulonglong2 cbp = *(const ulonglong2*)(g_cbP + (d4*512 + e)*4);
        #pragma unroll
        for (int g=0; g<16; g++){
            ulonglong2 zz = *(const ulonglong2*)(zsh + g*128 + d4*4);
            ffma2(acc[g], cbp.x, zz.x);
            ffma2(acc[g], cbp.y, zz.y);
        }
    }
    const float cbn = g_cbnorm[e];
    #pragma unroll
    for (int g=0; g<16; g++){
        float2 a = unpack2(acc[g]);
        float dot2 = a.x + a.y;
        float t1 = znorm[g] - dot2;
        float d  = t1 + cbn;
        unsigned u = __float_as_uint(d);
        unsigned mono = (u & 0x80000000u) ? ~u : (u | 0x80000000u);
        u64 key = ((u64)mono << 32) | (unsigned)e;
        #pragma unroll
        for (int o=16;o;o>>=1){
            u64 other = __shfl_down_sync(0xFFFFFFFFu, key, o);
            key = (other < key) ? other : key;
        }
        if (lane == 0) atomicMin(&smin[g], key);
    }
    __syncthreads();
    if (tid < 16){
        const int g = tid;
        u64 key = smin[g];
        unsigned mono = (unsigned)(key >> 32);
        unsigned u = (mono & 0x80000000u) ? (mono ^ 0x80000000u) : ~mono;
        float d = __uint_as_float(u);
        int idx = (int)(key & 0xFFFFFFFFu);
        if (vld[g]){
            g_idx[msh[g]] = idx;
            vqs[g] = (1.25f/128.f) * d * imask[msh[g]];
        } else {
            vqs[g] = 0.f;
        }
    }
    __syncthreads();
    if (tid == 0){
        float s = 0.f;
        #pragma unroll
        for (int g=0; g<16; g++) s += vqs[g];
        g_vqpart[blk] = s;
    }
}

// ---------------- gather + masked-MSE partials + folded finalize ----------------
__global__ void __launch_bounds__(256) out_kernel(const float* __restrict__ x,
                                                  const float* __restrict__ traj,
                                                  const float* __restrict__ imask,
                                                  float* __restrict__ out, int full){
    __shared__ float swd[8], sww[8], sim[8];
    __shared__ int slast;
    const int tid = threadIdx.x, wid = tid >> 5, lane = tid & 31;
    const int m = blockIdx.x*8 + wid;
    const float im = imask[m];
    const int sel = (im > 0.f) ? g_idx[m] : 512;
    const float* dec = g_decoded + sel*100;
    float sdw = 0.f, sw = 0.f;
    for (int t=lane; t<100; t+=32){
        float xh = dec[t];
        float xv = x[m*100 + t];
        float w  = im * traj[m*100 + t];
        out[m*100 + t] = xh;
        float df = xh - xv;
        sdw = fmaf(df*df, w, sdw);
        sw += w;
    }
    #pragma unroll
    for (int o=16;o;o>>=1){
        sdw += __shfl_down_sync(0xFFFFFFFFu, sdw, o);
        sw  += __shfl_down_sync(0xFFFFFFFFu, sw,  o);
    }
    if (lane == 0){
        swd[wid] = sdw; sww[wid] = sw; sim[wid] = im;
        if (full) out[OFF_IDX + m] = (im > 0.f) ? (float)g_idx[m] : -1.0f;
    }
    __syncthreads();
    if (tid == 0){
        float a=0.f,b=0.f,c=0.f;
        #pragma unroll
        for (int w2=0; w2<8; w2++){ a += swd[w2]; b += sww[w2]; c += sim[w2]; }
        g_rpart[blockIdx.x*3 + 0] = a;
        g_rpart[blockIdx.x*3 + 1] = b;
        g_rpart[blockIdx.x*3 + 2] = c;
        __threadfence();
        int t = atomicAdd(&g_done, 1);
        slast = (t == (int)gridDim.x - 1);
    }
    __syncthreads();
    if (!slast) return;

    // ---- folded finalize (deterministic: one block, fixed order) ----
    __shared__ float sd[256], sw2[256], si[256], sv[256];
    float a=0.f,b=0.f,c=0.f,v=0.f;
    for (int i=tid; i<6400; i+=256){
        a += __ldcg(&g_rpart[i*3 + 0]);
        b += __ldcg(&g_rpart[i*3 + 1]);
        c += __ldcg(&g_rpart[i*3 + 2]);
    }
    for (int i=tid; i<3200; i+=256) v += __ldcg(&g_vqpart[i]);
    sd[tid]=a; sw2[tid]=b; si[tid]=c; sv[tid]=v;
    __syncthreads();
    for (int o=128;o;o>>=1){
        if (tid < o){ sd[tid]+=sd[tid+o]; sw2[tid]+=sw2[tid+o]; si[tid]+=si[tid+o]; sv[tid]+=sv[tid+o]; }
        __syncthreads();
    }
    if (tid == 0 && full){
        out[OFF_RECON] = sd[0] / fmaxf(sw2[0], 1.f);
        out[OFF_VQ]    = sv[0] / fmaxf(si[0], 1.f);
    }
}

// ---------------- launch ----------------
extern "C" void kernel_launch(void* const* d_in, const int* in_sizes, int n_in,
                              void* d_out, int out_size){
    const float* x    = (const float*)d_in[0];
    const float* traj = (const float*)d_in[1];
    const float* im   = (const float*)d_in[2];
    const float* c1w  = (const float*)d_in[3];
    const float* c1b  = (const float*)d_in[4];
    const float* c2w  = (const float*)d_in[5];
    const float* c2b  = (const float*)d_in[6];
    const float* latw = (const float*)d_in[7];
    const float* latb = (const float*)d_in[8];
    const float* cb   = (const float*)d_in[9];
    const float* d1w  = (const float*)d_in[10];
    const float* d1b  = (const float*)d_in[11];
    const float* d2w  = (const float*)d_in[12];
    const float* d2b  = (const float*)d_in[13];
    const float* d3w  = (const float*)d_in[14];
    const float* d3b  = (const float*)d_in[15];
    float* out = (float*)d_out;
    const int full = (out_size >= OUT_FULL) ? 1 : 0;

    prep_kernel<<<132, 256>>>(c2w, latw, cb, d1w, d2w, d3w, im);
    compactC<<<50, 1024>>>(im);
    enc_kernel<<<Mm + 513, 128>>>(x, traj, im, c1w, c1b, c2b, latb, cb, d1b, d2b, d3b);
    vq_kernel<<<Mm/16, 512>>>(im);
    out_kernel<<<Mm/8, 256>>>(x, traj, im, out, full);
}

// round 16
// speedup vs baseline: 1.1465x; 1.0351x over previous
#include <cuda_runtime.h>
#include <cuda_bf16.h>
#include <cstdint>

// ---------------- problem constants ----------------
#define Bb 512
#define Nn 100
#define Tt 100
#define Mm (Bb*Nn)            // 51200
#define OFF_RECON  (Mm*Tt)
#define OFF_VQ     (Mm*Tt + 1)
#define OFF_IDX    (Mm*Tt + 2)
#define OUT_FULL   (Mm*Tt + 2 + Mm)

typedef unsigned long long u64;

// ---------------- scratch ----------------
__device__ __align__(16) float g_z[Mm*128];
__device__ int   g_idx[Mm];
__device__ __align__(16) float4 g_w4a[64*32];        // [ic][lane] = {w0A,w0B,w1A,w1B}
__device__ __align__(16) float2 g_w4b[64*32];        // [ic][lane] = {w2A,w2B}
__device__ __align__(16) float g_latT[64*128];
__device__ __align__(16) float g_cbP[512*128];
__device__ float g_cbnorm[512];
__device__ __align__(16) float g_d1T[128*256];
__device__ __align__(16) float g_d2T[256*256];
__device__ __align__(16) float g_d3T[256*100];
__device__ float g_decoded[513*100];
__device__ float g_vqpart[3200];
__device__ float g_rpart[6400*3];
__device__ int g_bcnt[50];
__device__ int g_cidx[Mm];
__device__ int g_nact;
__device__ int g_done;

// ---------------- f32x2 helpers ----------------
__device__ __forceinline__ u64 pack2(float a, float b){
    u64 r; asm("mov.b64 %0, {%1,%2};" : "=l"(r) : "f"(a), "f"(b)); return r;
}
__device__ __forceinline__ void ffma2(u64 &d, u64 a, u64 b){
    asm("fma.rn.f32x2 %0, %1, %2, %0;" : "+l"(d) : "l"(a), "l"(b));
}
__device__ __forceinline__ float2 unpack2(u64 v){
    float2 f; asm("mov.b64 {%0,%1}, %2;" : "=f"(f.x), "=f"(f.y) : "l"(v)); return f;
}

// ---------------- prep (+ folded compactA) ----------------
__global__ void prep_kernel(const float* __restrict__ c2w, const float* __restrict__ latw,
                            const float* __restrict__ cb,  const float* __restrict__ d1w,
                            const float* __restrict__ d2w, const float* __restrict__ d3w,
                            const float* __restrict__ imask){
    __shared__ int wc[8];
    int gt = blockIdx.x*blockDim.x + threadIdx.x;
    int nt = gridDim.x*blockDim.x;
    if (gt == 0) g_done = 0;
    if (blockIdx.x < 50){
        const int tid = threadIdx.x;
        int cnt = 0;
        #pragma unroll
        for (int j=0;j<4;j++){
            int m = blockIdx.x*1024 + j*256 + tid;
            unsigned b = __ballot_sync(0xFFFFFFFFu, imask[m] != 0.f);
            if ((tid & 31) == 0) cnt += __popc(b);
        }
        if ((tid & 31) == 0) wc[tid>>5] = 0;
        __syncthreads();
        if ((tid & 31) == 0) atomicAdd(&wc[tid>>5], cnt);
        __syncthreads();
        if (tid == 0){
            int s = 0;
            #pragma unroll
            for (int i=0;i<8;i++) s += wc[i];
            g_bcnt[blockIdx.x] = s;
        }
    }
    for (int i=gt; i<64*32; i+=nt){
        int lane = i & 31; int ic = i >> 5;
        g_w4a[i] = make_float4(c2w[lane*192 + ic*3 + 0], c2w[(lane+32)*192 + ic*3 + 0],
                               c2w[lane*192 + ic*3 + 1], c2w[(lane+32)*192 + ic*3 + 1]);
        g_w4b[i] = make_float2(c2w[lane*192 + ic*3 + 2], c2w[(lane+32)*192 + ic*3 + 2]);
    }
    for (int i=gt; i<64*128; i+=nt){
        int e = i & 127; int oc = i >> 7;
        g_latT[i] = latw[e*64 + oc];
    }
    for (int i=gt; i<512*128; i+=nt){
        int j = i & 3; int r = i >> 2; int e = r & 511; int d4 = r >> 9;
        g_cbP[i] = cb[e*128 + d4*4 + j];
    }
    for (int e=gt; e<512; e+=nt){
        float s = 0.f;
        for (int d=0; d<128; d++){ float v = cb[e*128+d]; s = fmaf(v,v,s); }
        g_cbnorm[e] = s;
    }
    for (int i=gt; i<128*256; i+=nt){ int j=i&255; int k=i>>8; g_d1T[i] = d1w[j*128+k]; }
    for (int i=gt; i<256*256; i+=nt){ int j=i&255; int k=i>>8; g_d2T[i] = d2w[j*256+k]; }
    for (int i=gt; i<256*100; i+=nt){ int j=i%100; int k=i/100; g_d3T[i] = d3w[j*256+k]; }
}

// ---------------- compaction scatter ----------------
__global__ void __launch_bounds__(1024) compactC(const float* __restrict__ imask){
    __shared__ int woff[32];
    __shared__ int sbase;
    const int tid = threadIdx.x;
    const int bid = blockIdx.x;
    const int m = bid*1024 + tid;
    const bool act = imask[m] != 0.f;
    unsigned b = __ballot_sync(0xFFFFFFFFu, act);
    if ((tid & 31) == 0) woff[tid>>5] = __popc(b);
    __syncthreads();
    if (tid == 0){
        int base = 0;
        for (int i=0;i<bid;i++) base += g_bcnt[i];
        sbase = base;
        int run = 0;
        #pragma unroll
        for (int w=0;w<32;w++){ int c = woff[w]; woff[w] = run; run += c; }
        if (bid == 0){
            int tot = 0;
            #pragma unroll
            for (int i=0;i<50;i++) tot += g_bcnt[i];
            g_nact = tot;
        }
    }
    __syncthreads();
    if (act){
        int rank = __popc(b & ((1u << (tid & 31)) - 1u));
        g_cidx[sbase + woff[tid>>5] + rank] = m;
    }
}

// ---------------- encoder (R15) + decode in spare blocks ----------------
#define HROW 52
// shh: h[l] at q=l (q in [0,49]); shs: h[l] at q=l+1, pads q=0 (h[-1]=0), q=51 (h[50]=0)

template<int NP>
__device__ __forceinline__ void conv2_tile(int lane, int l0, u64 bbA, u64 bbB,
                                           const float* __restrict__ shh,
                                           const float* __restrict__ shs,
                                           float &outA, float &outB){
    constexpr int NK = NP/2;
    u64 accA[NP], accB[NP];
    #pragma unroll
    for (int p=0;p<NP;p++){ accA[p]=bbA; accB[p]=bbB; }
    #pragma unroll 4
    for (int ic=0; ic<64; ic++){
        float4 w01 = g_w4a[ic*32 + lane];
        float2 w2  = g_w4b[ic*32 + lane];
        u64 W0a = pack2(w01.x,w01.x), W0b = pack2(w01.y,w01.y);
        u64 W1a = pack2(w01.z,w01.z), W1b = pack2(w01.w,w01.w);
        u64 W2a = pack2(w2.x,w2.x),   W2b = pack2(w2.y,w2.y);
        const float* hr = shh + ic*HROW + l0;
        const float* sr = shs + ic*HROW + l0;
        ulonglong2 Sc = *(const ulonglong2*)(sr);
        #pragma unroll
        for (int k=0;k<NK;k++){
            ulonglong2 A2 = *(const ulonglong2*)(hr + 4*k);
            ulonglong2 Sn = *(const ulonglong2*)(sr + 4*k + 4);
            const int p = 2*k;
            ffma2(accA[p], W0a, Sc.x); ffma2(accB[p], W0b, Sc.x);
            ffma2(accA[p], W1a, A2.x); ffma2(accB[p], W1b, A2.x);
            ffma2(accA[p], W2a, Sc.y); ffma2(accB[p], W2b, Sc.y);
            ffma2(accA[p+1], W0a, Sc.y); ffma2(accB[p+1], W0b, Sc.y);
            ffma2(accA[p+1], W1a, A2.y); ffma2(accB[p+1], W1b, A2.y);
            ffma2(accA[p+1], W2a, Sn.x); ffma2(accB[p+1], W2b, Sn.x);
            Sc = Sn;
        }
        if (NP & 1){
            const int p = NP - 1;
            u64 Atl = *(const u64*)(hr + 2*p);
            ffma2(accA[p], W0a, Sc.x); ffma2(accB[p], W0b, Sc.x);
            ffma2(accA[p], W1a, Atl);  ffma2(accB[p], W1b, Atl);
            ffma2(accA[p], W2a, Sc.y); ffma2(accB[p], W2b, Sc.y);
        }
    }
    float sA = 0.f, sB = 0.f;
    #pragma unroll
    for (int p=0;p<NP;p++){
        float2 fa = unpack2(accA[p]);
        float2 fb = unpack2(accB[p]);
        sA += fmaxf(fa.x,0.f) + fmaxf(fa.y,0.f);
        sB += fmaxf(fb.x,0.f) + fmaxf(fb.y,0.f);
    }
    outA = sA; outB = sB;
}

__global__ void __launch_bounds__(128) enc_kernel(const float* __restrict__ x,
                                                  const float* __restrict__ traj,
                                                  const float* __restrict__ imask,
                                                  const float* __restrict__ c1w,
                                                  const float* __restrict__ c1b,
                                                  const float* __restrict__ c2b,
                                                  const float* __restrict__ latb,
                                                  const float* __restrict__ cb,
                                                  const float* __restrict__ d1b,
                                                  const float* __restrict__ d2b,
                                                  const float* __restrict__ d3b){
    __shared__ __align__(16) float xs[112];
    __shared__ __align__(16) float shh[64*HROW];
    __shared__ __align__(16) float shs[64*HROW];
    float* phmA = shh;          // aliased (dead after conv2)
    float* hmsA = shh + 256;
    const int tid = threadIdx.x;
    const int nact = g_nact;
    const int s = blockIdx.x;

    if (s >= nact){
        const int e = s - nact;
        if (e >= 513) return;
        float* dv  = shh;
        float* dh2 = shh + 128;
        float* dh3 = shh + 384;
        dv[tid] = (e < 512) ? cb[e*128 + tid] : 0.f;
        __syncthreads();
        #pragma unroll
        for (int jj=0; jj<2; jj++){
            const int j = tid + jj*128;
            float a0=0.f,a1=0.f,a2=0.f,a3=0.f;
            #pragma unroll 4
            for (int k=0;k<128;k+=4){
                a0 = fmaf(g_d1T[(k+0)*256 + j], dv[k+0], a0);
                a1 = fmaf(g_d1T[(k+1)*256 + j], dv[k+1], a1);
                a2 = fmaf(g_d1T[(k+2)*256 + j], dv[k+2], a2);
                a3 = fmaf(g_d1T[(k+3)*256 + j], dv[k+3], a3);
            }
            dh2[j] = fmaxf(d1b[j] + ((a0+a1)+(a2+a3)), 0.f);
        }
        __syncthreads();
        #pragma unroll
        for (int jj=0; jj<2; jj++){
            const int j = tid + jj*128;
            float a0=0.f,a1=0.f,a2=0.f,a3=0.f;
            #pragma unroll 4
            for (int k=0;k<256;k+=4){
                a0 = fmaf(g_d2T[(k+0)*256 + j], dh2[k+0], a0);
                a1 = fmaf(g_d2T[(k+1)*256 + j], dh2[k+1], a1);
                a2 = fmaf(g_d2T[(k+2)*256 + j], dh2[k+2], a2);
                a3 = fmaf(g_d2T[(k+3)*256 + j], dh2[k+3], a3);
            }
            dh3[j] = fmaxf(d2b[j] + ((a0+a1)+(a2+a3)), 0.f);
        }
        __syncthreads();
        if (tid < 100){
            float a0=0.f,a1=0.f,a2=0.f,a3=0.f;
            #pragma unroll 4
            for (int k=0;k<256;k+=4){
                a0 = fmaf(g_d3T[(k+0)*100 + tid], dh3[k+0], a0);
                a1 = fmaf(g_d3T[(k+1)*100 + tid], dh3[k+1], a1);
                a2 = fmaf(g_d3T[(k+2)*100 + tid], dh3[k+2], a2);
                a3 = fmaf(g_d3T[(k+3)*100 + tid], dh3[k+3], a3);
            }
            g_decoded[e*100 + tid] = d3b[tid] + ((a0+a1)+(a2+a3));
        }
        return;
    }

    const int m = g_cidx[s];
    const float im = imask[m];

    const int oc = tid & 63, half = tid >> 6;
    if (tid < 112){
        float v = 0.f;
        if (tid >= 2 && tid < 102) v = x[m*100 + tid - 2] * traj[m*100 + tid - 2] * im;
        xs[tid] = v;
    }
    {
        int r = tid >> 1;
        int q = (tid & 1) ? 51 : 0;
        shs[r*HROW + q] = 0.f;
    }

    float w1r[6];
    #pragma unroll
    for (int j=0;j<6;j++) w1r[j] = c1w[oc*6 + (j&1)*3 + (j>>1)];
    const float b1v = c1b[oc];
    __syncthreads();

    {
        const int ls = half ? 26 : 0, le = half ? 50 : 26;
        float* dh = shh + oc*HROW;
        float* ds = shs + oc*HROW + 1;
        float2 p0 = *(const float2*)(xs + 2*ls);
        float2 p1 = *(const float2*)(xs + 2*ls + 2);
        float2 p2 = *(const float2*)(xs + 2*ls + 4);
        #pragma unroll 2
        for (int l=ls; l<le; l++){
            float a = b1v;
            a = fmaf(w1r[0], p0.x, a);
            a = fmaf(w1r[1], p0.y, a);
            a = fmaf(w1r[2], p1.x, a);
            a = fmaf(w1r[3], p1.y, a);
            a = fmaf(w1r[4], p2.x, a);
            a = fmaf(w1r[5], p2.y, a);
            a = fmaxf(a, 0.f);
            dh[l] = a;
            ds[l] = a;
            p0 = p1; p1 = p2;
            if (l+1 < le) p2 = *(const float2*)(xs + 2*(l+1) + 4);
        }
    }
    __syncthreads();

    const int wid = tid >> 5, lane = tid & 31;
    const float bA = c2b[lane], bB = c2b[lane+32];
    const u64 bbA = pack2(bA,bA), bbB = pack2(bB,bB);
    float sA, sB;
    if      (wid == 0) conv2_tile<6>(lane, 0,  bbA, bbB, shh, shs, sA, sB);
    else if (wid == 1) conv2_tile<6>(lane, 12, bbA, bbB, shh, shs, sA, sB);
    else if (wid == 2) conv2_tile<6>(lane, 24, bbA, bbB, shh, shs, sA, sB);
    else               conv2_tile<7>(lane, 36, bbA, bbB, shh, shs, sA, sB);
    __syncthreads();
    phmA[wid*64 + lane]      = sA;
    phmA[wid*64 + lane + 32] = sB;
    __syncthreads();
    if (tid < 64)
        hmsA[tid] = (((phmA[tid] + phmA[64 + tid]) + phmA[128 + tid]) + phmA[192 + tid]) * (1.f/50.f);
    __syncthreads();

    float acc = latb[tid];
    #pragma unroll 4
    for (int o2=0; o2<64; o2++) acc = fmaf(g_latT[o2*128 + tid], hmsA[o2], acc);
    g_z[m*128 + tid] = acc * im;
}

// ---------------- VQ: launch_bounds(512,2) + cbP prefetch; arithmetic unchanged ----------------
__global__ void __launch_bounds__(512, 2) vq_kernel(const float* __restrict__ imask){
    __shared__ __align__(16) float zsh[16*128];
    __shared__ u64 smin[16];
    __shared__ float znorm[16];
    __shared__ float vqs[16];
    __shared__ int msh[16];
    __shared__ int vld[16];
    const int tid = threadIdx.x;
    const int blk = blockIdx.x;
    const int nact = g_nact;
    const int s0 = blk * 16;
    if (s0 >= nact){
        if (tid == 0) g_vqpart[blk] = 0.f;
        return;
    }
    if (tid < 16){
        int s = s0 + tid;
        int valid = (s < nact);
        msh[tid] = valid ? g_cidx[s] : g_cidx[0];
        vld[tid] = valid;
        smin[tid] = ~0ULL;
    }
    __syncthreads();
    for (int i=tid; i<2048; i+=512){
        int m = msh[i >> 7];
        zsh[i] = 2.0f * g_z[m*128 + (i & 127)];
    }
    __syncthreads();

    const int wid = tid >> 5, lane = tid & 31;
    {
        float s = 0.f;
        #pragma unroll
        for (int d=lane; d<128; d+=32){ float v = zsh[wid*128 + d]; s = fmaf(v,v,s); }
        #pragma unroll
        for (int o=16;o;o>>=1) s += __shfl_down_sync(0xFFFFFFFFu, s, o);
        if (lane == 0) znorm[wid] = 0.25f * s;
    }
    __syncthreads();

    const int e = tid;
    u64 acc[16];
    #pragma unroll
    for (int g=0; g<16; g++) acc[g] = 0ULL;
    ulonglong2 cbp = *(const ulonglong2*)(g_cbP + e*4);      // d4 = 0
    #pragma unroll 1
    for (int d4=0; d4<32; d4++){
        ulonglong2 cbn2 = cbp;
        if (d4 + 1 < 32) cbn2 = *(const ulonglong2*)(g_cbP + ((d4+1)*512 + e)*4);  // prefetch
        #pragma unroll
        for (int g=0; g<16; g++){
            ulonglong2 zz = *(const ulonglong2*)(zsh + g*128 + d4*4);
            ffma2(acc[g], cbp.x, zz.x);
            ffma2(acc[g], cbp.y, zz.y);
        }
        cbp = cbn2;
    }
    const float cbn = g_cbnorm[e];
    #pragma unroll
    for (int g=0; g<16; g++){
        float2 a = unpack2(acc[g]);
        float dot2 = a.x + a.y;
        float t1 = znorm[g] - dot2;
        float d  = t1 + cbn;
        unsigned u = __float_as_uint(d);
        unsigned mono = (u & 0x80000000u) ? ~u : (u | 0x80000000u);
        u64 key = ((u64)mono << 32) | (unsigned)e;
        #pragma unroll
        for (int o=16;o;o>>=1){
            u64 other = __shfl_down_sync(0xFFFFFFFFu, key, o);
            key = (other < key) ? other : key;
        }
        if (lane == 0) atomicMin(&smin[g], key);
    }
    __syncthreads();
    if (tid < 16){
        const int g = tid;
        u64 key = smin[g];
        unsigned mono = (unsigned)(key >> 32);
        unsigned u = (mono & 0x80000000u) ? (mono ^ 0x80000000u) : ~mono;
        float d = __uint_as_float(u);
        int idx = (int)(key & 0xFFFFFFFFu);
        if (vld[g]){
            g_idx[msh[g]] = idx;
            vqs[g] = (1.25f/128.f) * d * imask[msh[g]];
        } else {
            vqs[g] = 0.f;
        }
    }
    __syncthreads();
    if (tid == 0){
        float s = 0.f;
        #pragma unroll
        for (int g=0; g<16; g++) s += vqs[g];
        g_vqpart[blk] = s;
    }
}

// ---------------- gather + masked-MSE partials + folded finalize ----------------
__global__ void __launch_bounds__(256) out_kernel(const float* __restrict__ x,
                                                  const float* __restrict__ traj,
                                                  const float* __restrict__ imask,
                                                  float* __restrict__ out, int full){
    __shared__ float swd[8], sww[8], sim[8];
    __shared__ int slast;
    const int tid = threadIdx.x, wid = tid >> 5, lane = tid & 31;
    const int m = blockIdx.x*8 + wid;
    const float im = imask[m];
    const int sel = (im > 0.f) ? g_idx[m] : 512;
    const float* dec = g_decoded + sel*100;
    float sdw = 0.f, sw = 0.f;
    for (int t=lane; t<100; t+=32){
        float xh = dec[t];
        float xv = x[m*100 + t];
        float w  = im * traj[m*100 + t];
        out[m*100 + t] = xh;
        float df = xh - xv;
        sdw = fmaf(df*df, w, sdw);
        sw += w;
    }
    #pragma unroll
    for (int o=16;o;o>>=1){
        sdw += __shfl_down_sync(0xFFFFFFFFu, sdw, o);
        sw  += __shfl_down_sync(0xFFFFFFFFu, sw,  o);
    }
    if (lane == 0){
        swd[wid] = sdw; sww[wid] = sw; sim[wid] = im;
        if (full) out[OFF_IDX + m] = (im > 0.f) ? (float)g_idx[m] : -1.0f;
    }
    __syncthreads();
    if (tid == 0){
        float a=0.f,b=0.f,c=0.f;
        #pragma unroll
        for (int w2=0; w2<8; w2++){ a += swd[w2]; b += sww[w2]; c += sim[w2]; }
        g_rpart[blockIdx.x*3 + 0] = a;
        g_rpart[blockIdx.x*3 + 1] = b;
        g_rpart[blockIdx.x*3 + 2] = c;
        __threadfence();
        int t = atomicAdd(&g_done, 1);
        slast = (t == (int)gridDim.x - 1);
    }
    __syncthreads();
    if (!slast) return;

    __shared__ float sd[256], sw2[256], si[256], sv[256];
    float a=0.f,b=0.f,c=0.f,v=0.f;
    for (int i=tid; i<6400; i+=256){
        a += __ldcg(&g_rpart[i*3 + 0]);
        b += __ldcg(&g_rpart[i*3 + 1]);
        c += __ldcg(&g_rpart[i*3 + 2]);
    }
    for (int i=tid; i<3200; i+=256) v += __ldcg(&g_vqpart[i]);
    sd[tid]=a; sw2[tid]=b; si[tid]=c; sv[tid]=v;
    __syncthreads();
    for (int o=128;o;o>>=1){
        if (tid < o){ sd[tid]+=sd[tid+o]; sw2[tid]+=sw2[tid+o]; si[tid]+=si[tid+o]; sv[tid]+=sv[tid+o]; }
        __syncthreads();
    }
    if (tid == 0 && full){
        out[OFF_RECON] = sd[0] / fmaxf(sw2[0], 1.f);
        out[OFF_VQ]    = sv[0] / fmaxf(si[0], 1.f);
    }
}

// ---------------- launch ----------------
extern "C" void kernel_launch(void* const* d_in, const int* in_sizes, int n_in,
                              void* d_out, int out_size){
    const float* x    = (const float*)d_in[0];
    const float* traj = (const float*)d_in[1];
    const float* im   = (const float*)d_in[2];
    const float* c1w  = (const float*)d_in[3];
    const float* c1b  = (const float*)d_in[4];
    const float* c2w  = (const float*)d_in[5];
    const float* c2b  = (const float*)d_in[6];
    const float* latw = (const float*)d_in[7];
    const float* latb = (const float*)d_in[8];
    const float* cb   = (const float*)d_in[9];
    const float* d1w  = (const float*)d_in[10];
    const float* d1b  = (const float*)d_in[11];
    const float* d2w  = (const float*)d_in[12];
    const float* d2b  = (const float*)d_in[13];
    const float* d3w  = (const float*)d_in[14];
    const float* d3b  = (const float*)d_in[15];
    float* out = (float*)d_out;
    const int full = (out_size >= OUT_FULL) ? 1 : 0;

    prep_kernel<<<132, 256>>>(c2w, latw, cb, d1w, d2w, d3w, im);
    compactC<<<50, 1024>>>(im);
    enc_kernel<<<Mm + 513, 128>>>(x, traj, im, c1w, c1b, c2b, latb, cb, d1b, d2b, d3b);
    vq_kernel<<<Mm/16, 512>>>(im);
    out_kernel<<<Mm/8, 256>>>(x, traj, im, out, full);
}